// round 1
// baseline (speedup 1.0000x reference)
#include <cuda_runtime.h>
#include <cuda_bf16.h>

// ---- physical constants (double-precision derived, matching reference) ----
#define KEHALF      7.199822675975274f
#define CUTON_F     2.5f
#define CUTOFF_F    7.5f
#define LRCUT_F     10.0f
#define CUTON16_F   2328306.4365386963f     // 2.5^16
#define CUT_RCONST  0.009999999997526174f   // 10^15 / (10^16 + 2.5^16)^(17/16)
#define CUT_CONST   0.19999999999608f       // (2.5^16+10^16)^(-1/16) + 10^16/(10^16+2.5^16)^(17/16)
#define INV_RANGE   0.2f                    // 1/(CUTOFF-CUTON)
#define INV_LR2     0.01f                   // 1/LR_CUTOFF^2
#define TWO_OVER_LR 0.2f                    // 2/LR_CUTOFF

#define MAX_N 102400
#define MAX_M 2048

// scratch: packed (q[i], idx_m[i]) so the i-side gather is ONE 8B load (one L2 sector)
__device__ float2 d_qm[MAX_N];

__global__ void prep_kernel(const float* __restrict__ q,
                            const int* __restrict__ idx_m,
                            int N, float* __restrict__ out, int M) {
    int i = blockIdx.x * blockDim.x + threadIdx.x;
    if (i < N && i < MAX_N) d_qm[i] = make_float2(q[i], __int_as_float(idx_m[i]));
    if (i < M) out[i] = 0.0f;  // d_out is poisoned; zero it before atomics
}

__device__ __forceinline__ float edge_energy(float x, float y, float z,
                                             float qi, float qj) {
    float s  = fmaf(x, x, fmaf(y, y, z * z));   // d^2
    float rd = rsqrtf(s);                       // 1/d
    float d  = s * rd;                          // d
    float fac = KEHALF * qi * qj;

    // smooth switch: f = exp(-1/t) / (exp(-1/t) + exp(-1/(1-t))) = sigmoid(-(1/t - 1/(1-t)))
    float f;
    if (d >= CUTOFF_F) {
        f = 0.0f;
    } else if (d <= CUTON_F) {
        f = 1.0f;
    } else {
        float t = (CUTOFF_F - d) * INV_RANGE;   // in (0,1)
        float g = __fdividef(1.0f, t) - __fdividef(1.0f, 1.0f - t);
        f = __fdividef(1.0f, 1.0f + __expf(g));
    }

    // (d^16 + CUTON16)^(-1/16) via LG2/EX2 (2 MUFU instead of rsqrt-chain)
    float d4  = s * s;
    float d8  = d4 * d4;
    float d16 = d8 * d8;
    float p   = exp2f(-0.0625f * __log2f(d16 + CUTON16_F));

    float omf    = 1.0f - f;
    float damped = fmaf(omf * CUT_RCONST, d, p - CUT_CONST);
    float coul   = (d < LRCUT_F) ? (rd + fmaf(d, INV_LR2, -TWO_OVER_LR)) : 0.0f;
    return fac * fmaf(f, damped, omf * coul);
}

template <bool USE_SMEM>
__global__ __launch_bounds__(256)
void energy_kernel(const float4* __restrict__ r4,
                   const float*  __restrict__ q,
                   const int4*   __restrict__ ii4,
                   const int4*   __restrict__ jj4,
                   const float*  __restrict__ r_scalar,
                   const int*    __restrict__ idx_i,
                   const int*    __restrict__ idx_j,
                   int P, float* __restrict__ out, int M) {
    __shared__ float ymol[MAX_M];
    if (USE_SMEM) {
        for (int b = threadIdx.x; b < M; b += blockDim.x) ymol[b] = 0.0f;
        __syncthreads();
    }
    float* acc = USE_SMEM ? ymol : out;

    int gid    = blockIdx.x * blockDim.x + threadIdx.x;
    int stride = gridDim.x * blockDim.x;
    int P4 = P >> 2;

    for (int g = gid; g < P4; g += stride) {
        // coalesced streams: 4 edges = 3 float4 + 2 int4
        float4 a = r4[3 * g + 0];
        float4 b = r4[3 * g + 1];
        float4 c = r4[3 * g + 2];
        int4 ii = ii4[g];
        int4 jj = jj4[g];

        // issue all gathers first (independent -> MLP)
        float2 m0 = d_qm[ii.x];
        float2 m1 = d_qm[ii.y];
        float2 m2 = d_qm[ii.z];
        float2 m3 = d_qm[ii.w];
        float qj0 = __ldg(&q[jj.x]);
        float qj1 = __ldg(&q[jj.y]);
        float qj2 = __ldg(&q[jj.z]);
        float qj3 = __ldg(&q[jj.w]);

        float e0 = edge_energy(a.x, a.y, a.z, m0.x, qj0);
        float e1 = edge_energy(a.w, b.x, b.y, m1.x, qj1);
        float e2 = edge_energy(b.z, b.w, c.x, m2.x, qj2);
        float e3 = edge_energy(c.y, c.z, c.w, m3.x, qj3);

        atomicAdd(&acc[__float_as_int(m0.y)], e0);
        atomicAdd(&acc[__float_as_int(m1.y)], e1);
        atomicAdd(&acc[__float_as_int(m2.y)], e2);
        atomicAdd(&acc[__float_as_int(m3.y)], e3);
    }

    // scalar tail (P % 4 edges)
    for (int e = (P4 << 2) + gid; e < P; e += stride) {
        float x = r_scalar[3 * e + 0];
        float y = r_scalar[3 * e + 1];
        float z = r_scalar[3 * e + 2];
        float2 mi = d_qm[idx_i[e]];
        float qj  = __ldg(&q[idx_j[e]]);
        float ev  = edge_energy(x, y, z, mi.x, qj);
        atomicAdd(&acc[__float_as_int(mi.y)], ev);
    }

    if (USE_SMEM) {
        __syncthreads();
        for (int b = threadIdx.x; b < M; b += blockDim.x) {
            float v = ymol[b];
            if (v != 0.0f) atomicAdd(&out[b], v);
        }
    }
}

extern "C" void kernel_launch(void* const* d_in, const int* in_sizes, int n_in,
                              void* d_out, int out_size) {
    // metadata order: atomic_numbers, q, r_ij, idx_i, idx_j, idx_m, maxm
    const float* q     = (const float*)d_in[1];
    const float* r_ij  = (const float*)d_in[2];
    const int*   idx_i = (const int*)d_in[3];
    const int*   idx_j = (const int*)d_in[4];
    const int*   idx_m = (const int*)d_in[5];
    int N = in_sizes[1];
    int P = in_sizes[3];
    int M = out_size;
    float* out = (float*)d_out;

    int prep_elems = (N > M) ? N : M;
    prep_kernel<<<(prep_elems + 255) / 256, 256>>>(q, idx_m, N, out, M);

    const int threads = 256;
    const int blocks  = 1184;  // ~8 blocks per SM; grid-stride keeps flush-atomic count bounded
    if (M <= MAX_M) {
        energy_kernel<true><<<blocks, threads>>>(
            (const float4*)r_ij, q, (const int4*)idx_i, (const int4*)idx_j,
            r_ij, idx_i, idx_j, P, out, M);
    } else {
        energy_kernel<false><<<blocks, threads>>>(
            (const float4*)r_ij, q, (const int4*)idx_i, (const int4*)idx_j,
            r_ij, idx_i, idx_j, P, out, M);
    }
}